// round 5
// baseline (speedup 1.0000x reference)
#include <cuda_runtime.h>
#include <math.h>
#include <stdint.h>

#define BB 16
#define DD 128
#define LC 2048
#define LQ 512
#define NEGF (-1e30f)

// ---- scratch (device globals) ----
__device__ float g_S[(size_t)BB * LC * LQ];
__device__ float g_A[(size_t)BB * LC * DD];
__device__ float g_Bm[(size_t)BB * LC * DD];
__device__ float g_V2[(size_t)BB * LQ * DD];
__device__ float g_V2p[(size_t)4 * BB * LQ * DD];
__device__ float g_sub0[BB * LC];
__device__ float g_sub1[BB * LQ];
__device__ float g_rmax[BB * LC], g_rinv[BB * LC];
__device__ float g_cmax[BB * LQ], g_cinv[BB * LQ];
__device__ float g_cpm[4 * BB * LQ], g_cps[4 * BB * LQ];

// dynamic smem layout (floats): AH[32*132] AL BH BL AUX[768]
#define TSTR 132
#define TILE_F (32 * TSTR)
#define SMEM_FLOATS (4 * TILE_F + 768)
#define SMEM_BYTES (SMEM_FLOATS * 4)

__device__ __forceinline__ void tf32split(float x, float& h, float& l) {
    uint32_t u;
    asm("cvt.rna.tf32.f32 %0, %1;" : "=r"(u) : "f"(x));
    h = __uint_as_float(u);
    uint32_t v;
    asm("cvt.rna.tf32.f32 %0, %1;" : "=r"(v) : "f"(x - h));
    l = __uint_as_float(v);
}

#define MMA8(c, a, b)                                                        \
    asm volatile(                                                            \
        "mma.sync.aligned.m16n8k8.row.col.f32.tf32.tf32.f32 "                \
        "{%0,%1,%2,%3}, {%4,%5,%6,%7}, {%8,%9}, {%0,%1,%2,%3};"              \
        : "+f"((c)[0]), "+f"((c)[1]), "+f"((c)[2]), "+f"((c)[3])             \
        : "r"((a)[0]), "r"((a)[1]), "r"((a)[2]), "r"((a)[3]),                \
          "r"((b)[0]), "r"((b)[1]))

// one BK=32 chunk of 3x-split tf32 mma; warp tile 32(m) x 64(n)
__device__ __forceinline__ void mma_chunk(const float* AH, const float* AL,
                                          const float* BH, const float* BL,
                                          float acc[2][8][4],
                                          int mbase, int nbase, int lane) {
    int lq = lane >> 2, kq = lane & 3;
    #pragma unroll
    for (int ks = 0; ks < 4; ks++) {
        int k8 = ks * 8;
        uint32_t ah[2][4], al[2][4];
        #pragma unroll
        for (int ma = 0; ma < 2; ma++) {
            const float* p = AH + (k8 + kq) * TSTR + mbase + 16 * ma + lq;
            ah[ma][0] = *(const uint32_t*)(p);
            ah[ma][1] = *(const uint32_t*)(p + 8);
            ah[ma][2] = *(const uint32_t*)(p + 4 * TSTR);
            ah[ma][3] = *(const uint32_t*)(p + 4 * TSTR + 8);
            const float* q = AL + (k8 + kq) * TSTR + mbase + 16 * ma + lq;
            al[ma][0] = *(const uint32_t*)(q);
            al[ma][1] = *(const uint32_t*)(q + 8);
            al[ma][2] = *(const uint32_t*)(q + 4 * TSTR);
            al[ma][3] = *(const uint32_t*)(q + 4 * TSTR + 8);
        }
        #pragma unroll
        for (int ng = 0; ng < 2; ng++) {
            uint32_t bh[4][2], bl[4][2];
            #pragma unroll
            for (int na = 0; na < 4; na++) {
                int c0 = nbase + 32 * ng + 8 * na + lq;
                bh[na][0] = *(const uint32_t*)(BH + (k8 + kq) * TSTR + c0);
                bh[na][1] = *(const uint32_t*)(BH + (k8 + kq + 4) * TSTR + c0);
                bl[na][0] = *(const uint32_t*)(BL + (k8 + kq) * TSTR + c0);
                bl[na][1] = *(const uint32_t*)(BL + (k8 + kq + 4) * TSTR + c0);
            }
            #pragma unroll
            for (int ma = 0; ma < 2; ma++)
                #pragma unroll
                for (int na = 0; na < 4; na++) {
                    float* c = acc[ma][ng * 4 + na];
                    MMA8(c, ah[ma], bh[na]);
                    MMA8(c, ah[ma], bl[na]);
                    MMA8(c, al[ma], bh[na]);
                }
        }
    }
}

// ============================================================
// K0: sub0 / sub1
// ============================================================
__global__ void k_sub(const float* __restrict__ C, const float* __restrict__ Q,
                      const float* __restrict__ w4C, const float* __restrict__ w4Q,
                      const float* __restrict__ bias) {
    int t = blockIdx.x * blockDim.x + threadIdx.x;
    const int totC = BB * LC;
    if (t < totC) {
        int b = t / LC, c = t % LC;
        const float* Cp = C + (size_t)b * DD * LC + c;
        float s = 0.f;
        #pragma unroll 8
        for (int d = 0; d < DD; d++) s += Cp[(size_t)d * LC] * w4C[d];
        g_sub0[t] = s;
    } else if (t < totC + BB * LQ) {
        int u = t - totC;
        int b = u / LQ, q = u % LQ;
        const float* Qp = Q + (size_t)b * DD * LQ + q;
        float s = bias[0];
        #pragma unroll 8
        for (int d = 0; d < DD; d++) s += Qp[(size_t)d * LQ] * w4Q[d];
        g_sub1[u] = s;
    }
}

// ============================================================
// K1: S = (C*w)^T Q + sub0 + sub1   [m=c, n=q, k=d(128)]
// ============================================================
__global__ __launch_bounds__(256, 2) void k_scores(const float* __restrict__ C,
                                                   const float* __restrict__ Q,
                                                   const float* __restrict__ w4mlu) {
    extern __shared__ float smf[];
    float* AH = smf;
    float* AL = AH + TILE_F;
    float* BH = AL + TILE_F;
    float* BL = BH + TILE_F;
    float* AUX = BL + TILE_F;
    int tid = threadIdx.x, wid = tid >> 5, lane = tid & 31;
    int b = blockIdx.z, cb = blockIdx.y * 128, qb = blockIdx.x * 128;
    int mbase = (wid >> 1) * 32, nbase = (wid & 1) * 64;
    const float* Cb = C + (size_t)b * DD * LC + cb;
    const float* Qb = Q + (size_t)b * DD * LQ + qb;

    if (tid < 128) {
        AUX[tid] = g_sub0[b * LC + cb + tid];
        AUX[128 + tid] = g_sub1[b * LQ + qb + tid];
    }

    float acc[2][8][4];
    #pragma unroll
    for (int i = 0; i < 2; i++)
        #pragma unroll
        for (int j = 0; j < 8; j++)
            #pragma unroll
            for (int r = 0; r < 4; r++) acc[i][j][r] = 0.f;

    for (int k0 = 0; k0 < DD; k0 += 32) {
        #pragma unroll
        for (int p = 0; p < 4; p++) {
            int r = (tid >> 5) + p * 8;
            int c4 = (tid & 31) * 4;
            float w = w4mlu[k0 + r];
            float4 cv = *(const float4*)(Cb + (size_t)(k0 + r) * LC + c4);
            float4 h, l;
            tf32split(cv.x * w, h.x, l.x); tf32split(cv.y * w, h.y, l.y);
            tf32split(cv.z * w, h.z, l.z); tf32split(cv.w * w, h.w, l.w);
            *(float4*)(AH + r * TSTR + c4) = h;
            *(float4*)(AL + r * TSTR + c4) = l;
            float4 qv = *(const float4*)(Qb + (size_t)(k0 + r) * LQ + c4);
            tf32split(qv.x, h.x, l.x); tf32split(qv.y, h.y, l.y);
            tf32split(qv.z, h.z, l.z); tf32split(qv.w, h.w, l.w);
            *(float4*)(BH + r * TSTR + c4) = h;
            *(float4*)(BL + r * TSTR + c4) = l;
        }
        __syncthreads();
        mma_chunk(AH, AL, BH, BL, acc, mbase, nbase, lane);
        __syncthreads();
    }

    int lq = lane >> 2, kq = lane & 3;
    #pragma unroll
    for (int ma = 0; ma < 2; ma++)
        #pragma unroll
        for (int na = 0; na < 8; na++) {
            int r = mbase + 16 * ma + lq;
            int col = nbase + 8 * na + kq * 2;
            float s1a = AUX[128 + col], s1b = AUX[128 + col + 1];
            float* o0 = g_S + ((size_t)b * LC + cb + r) * LQ + qb + col;
            float* o1 = g_S + ((size_t)b * LC + cb + r + 8) * LQ + qb + col;
            float s0a = AUX[r], s0b = AUX[r + 8];
            *(float2*)o0 = make_float2(acc[ma][na][0] + s0a + s1a,
                                       acc[ma][na][1] + s0a + s1b);
            *(float2*)o1 = make_float2(acc[ma][na][2] + s0b + s1a,
                                       acc[ma][na][3] + s0b + s1b);
        }
}

// ============================================================
// stats
// ============================================================
__global__ void k_rowstats(const int* __restrict__ Qmask) {
    int w = blockIdx.x * 8 + (threadIdx.x >> 5);
    int lane = threadIdx.x & 31;
    if (w >= BB * LC) return;
    int b = w / LC;
    const float* Sp = g_S + (size_t)w * LQ;
    const int* qm = Qmask + b * LQ;
    float vals[16], m = -INFINITY;
    #pragma unroll
    for (int i = 0; i < 16; i++) {
        int q = lane + 32 * i;
        float v = Sp[q];
        if (!qm[q]) v += NEGF;
        vals[i] = v; m = fmaxf(m, v);
    }
    #pragma unroll
    for (int o = 16; o > 0; o >>= 1) m = fmaxf(m, __shfl_xor_sync(~0u, m, o));
    float s = 0.f;
    #pragma unroll
    for (int i = 0; i < 16; i++) s += __expf(vals[i] - m);
    #pragma unroll
    for (int o = 16; o > 0; o >>= 1) s += __shfl_xor_sync(~0u, s, o);
    if (lane == 0) { g_rmax[w] = m; g_rinv[w] = 1.f / s; }
}

__global__ void k_colstats_part(const int* __restrict__ Cmask) {
    __shared__ float sm[8][33], ss[8][33];
    __shared__ float cadd[512];
    int b = blockIdx.z, chunk = blockIdx.y * 512;
    int lane = threadIdx.x & 31, yg = threadIdx.x >> 5;
    for (int i = threadIdx.x; i < 512; i += 256)
        cadd[i] = Cmask[b * LC + chunk + i] ? 0.f : NEGF;
    __syncthreads();
    int q = blockIdx.x * 32 + lane, cl = yg * 64;
    const float* Sp = g_S + (size_t)b * LC * LQ + (size_t)(chunk + cl) * LQ + q;
    float m = -INFINITY, s = 0.f;
    #pragma unroll 4
    for (int i = 0; i < 16; i++) {
        const float* p = Sp + (size_t)i * 4 * LQ;
        float v0 = p[0] + cadd[cl + i * 4], v1 = p[LQ] + cadd[cl + i * 4 + 1];
        float v2 = p[2 * LQ] + cadd[cl + i * 4 + 2], v3 = p[3 * LQ] + cadd[cl + i * 4 + 3];
        float mn = fmaxf(m, fmaxf(fmaxf(v0, v1), fmaxf(v2, v3)));
        s = s * __expf(m - mn) + __expf(v0 - mn) + __expf(v1 - mn)
                               + __expf(v2 - mn) + __expf(v3 - mn);
        m = mn;
    }
    sm[yg][lane] = m; ss[yg][lane] = s;
    __syncthreads();
    if (yg == 0) {
        float M = m, S = s;
        #pragma unroll
        for (int g = 1; g < 8; g++) {
            float m2 = sm[g][lane], s2 = ss[g][lane], mn = fmaxf(M, m2);
            S = S * __expf(M - mn) + s2 * __expf(m2 - mn); M = mn;
        }
        int idx = (blockIdx.y * BB + b) * LQ + q;
        g_cpm[idx] = M; g_cps[idx] = S;
    }
}

__global__ void k_colstats_merge() {
    int t = blockIdx.x * 256 + threadIdx.x;
    if (t >= BB * LQ) return;
    float M = -INFINITY, S = 0.f;
    #pragma unroll
    for (int g = 0; g < 4; g++) {
        float m2 = g_cpm[g * BB * LQ + t], s2 = g_cps[g * BB * LQ + t], mn = fmaxf(M, m2);
        S = S * __expf(M - mn) + s2 * __expf(m2 - mn); M = mn;
    }
    g_cmax[t] = M; g_cinv[t] = 1.f / S;
}

// ============================================================
// K3: A = S1 @ Qt  [m=c, n=d, k=q(512)]
// ============================================================
__global__ __launch_bounds__(256, 2) void k_gemmA(const float* __restrict__ Q,
                                                  const int* __restrict__ Qmask) {
    extern __shared__ float smf[];
    float* AH = smf;
    float* AL = AH + TILE_F;
    float* BH = AL + TILE_F;
    float* BL = BH + TILE_F;
    float* AUX = BL + TILE_F;
    int tid = threadIdx.x, wid = tid >> 5, lane = tid & 31;
    int b = blockIdx.y, cb = blockIdx.x * 128;
    int mbase = (wid >> 1) * 32, nbase = (wid & 1) * 64;

    if (tid < 128) {
        AUX[tid] = g_rmax[b * LC + cb + tid];
        AUX[128 + tid] = g_rinv[b * LC + cb + tid];
    }
    for (int i = tid; i < 512; i += 256) AUX[256 + i] = Qmask[b * LQ + i] ? 0.f : NEGF;
    __syncthreads();

    float acc[2][8][4];
    #pragma unroll
    for (int i = 0; i < 2; i++)
        #pragma unroll
        for (int j = 0; j < 8; j++)
            #pragma unroll
            for (int r = 0; r < 4; r++) acc[i][j][r] = 0.f;

    const float* Qb = Q + (size_t)b * DD * LQ;
    const float* Sb = g_S + ((size_t)b * LC + cb) * LQ;

    for (int k0 = 0; k0 < LQ; k0 += 32) {
        #pragma unroll
        for (int p = 0; p < 4; p++) {
            int row = (tid >> 3) + p * 32;
            int qq = (tid & 7) * 4;
            float4 v = *(const float4*)(Sb + (size_t)row * LQ + k0 + qq);
            float rm = AUX[row], ri = AUX[128 + row];
            float h, l, e;
            e = __expf(v.x + AUX[256 + k0 + qq + 0] - rm) * ri; tf32split(e, h, l);
            AH[(qq + 0) * TSTR + row] = h; AL[(qq + 0) * TSTR + row] = l;
            e = __expf(v.y + AUX[256 + k0 + qq + 1] - rm) * ri; tf32split(e, h, l);
            AH[(qq + 1) * TSTR + row] = h; AL[(qq + 1) * TSTR + row] = l;
            e = __expf(v.z + AUX[256 + k0 + qq + 2] - rm) * ri; tf32split(e, h, l);
            AH[(qq + 2) * TSTR + row] = h; AL[(qq + 2) * TSTR + row] = l;
            e = __expf(v.w + AUX[256 + k0 + qq + 3] - rm) * ri; tf32split(e, h, l);
            AH[(qq + 3) * TSTR + row] = h; AL[(qq + 3) * TSTR + row] = l;
            // B: Q[d=row][q] transposed
            float4 w = *(const float4*)(Qb + (size_t)row * LQ + k0 + qq);
            tf32split(w.x, h, l); BH[(qq + 0) * TSTR + row] = h; BL[(qq + 0) * TSTR + row] = l;
            tf32split(w.y, h, l); BH[(qq + 1) * TSTR + row] = h; BL[(qq + 1) * TSTR + row] = l;
            tf32split(w.z, h, l); BH[(qq + 2) * TSTR + row] = h; BL[(qq + 2) * TSTR + row] = l;
            tf32split(w.w, h, l); BH[(qq + 3) * TSTR + row] = h; BL[(qq + 3) * TSTR + row] = l;
        }
        __syncthreads();
        mma_chunk(AH, AL, BH, BL, acc, mbase, nbase, lane);
        __syncthreads();
    }

    int lq = lane >> 2, kq = lane & 3;
    float* Ab = g_A + ((size_t)b * LC + cb) * DD;
    #pragma unroll
    for (int ma = 0; ma < 2; ma++)
        #pragma unroll
        for (int na = 0; na < 8; na++) {
            int r = mbase + 16 * ma + lq;
            int col = nbase + 8 * na + kq * 2;
            *(float2*)(Ab + (size_t)r * DD + col) =
                make_float2(acc[ma][na][0], acc[ma][na][1]);
            *(float2*)(Ab + (size_t)(r + 8) * DD + col) =
                make_float2(acc[ma][na][2], acc[ma][na][3]);
        }
}

// ============================================================
// K4: V2 partials [m=q, n=d, k=c(512/part)]
// ============================================================
__global__ __launch_bounds__(256, 2) void k_gemmV2(const float* __restrict__ C,
                                                   const int* __restrict__ Cmask) {
    extern __shared__ float smf[];
    float* AH = smf;
    float* AL = AH + TILE_F;
    float* BH = AL + TILE_F;
    float* BL = BH + TILE_F;
    float* AUX = BL + TILE_F;
    int tid = threadIdx.x, wid = tid >> 5, lane = tid & 31;
    int b = blockIdx.z, part = blockIdx.y, qb = blockIdx.x * 128;
    int mbase = (wid >> 1) * 32, nbase = (wid & 1) * 64;
    int c0chunk = part * 512;

    if (tid < 128) {
        AUX[tid] = g_cmax[b * LQ + qb + tid];
        AUX[128 + tid] = g_cinv[b * LQ + qb + tid];
    }
    for (int i = tid; i < 512; i += 256) AUX[256 + i] = Cmask[b * LC + c0chunk + i] ? 0.f : NEGF;
    __syncthreads();

    float acc[2][8][4];
    #pragma unroll
    for (int i = 0; i < 2; i++)
        #pragma unroll
        for (int j = 0; j < 8; j++)
            #pragma unroll
            for (int r = 0; r < 4; r++) acc[i][j][r] = 0.f;

    const float* Cb = C + (size_t)b * DD * LC;
    const float* Sb = g_S + ((size_t)b * LC + c0chunk) * LQ + qb;

    for (int k0 = 0; k0 < 512; k0 += 32) {
        #pragma unroll
        for (int p = 0; p < 4; p++) {
            // A: exp(S2)[c][q] direct rows (k=c)
            int kk = (tid >> 5) + p * 8;
            int q4 = (tid & 31) * 4;
            float4 v = *(const float4*)(Sb + (size_t)(k0 + kk) * LQ + q4);
            float ca = AUX[256 + k0 + kk];
            float4 h4, l4;
            float e;
            e = __expf(v.x + ca - AUX[q4 + 0]) * AUX[128 + q4 + 0]; tf32split(e, h4.x, l4.x);
            e = __expf(v.y + ca - AUX[q4 + 1]) * AUX[128 + q4 + 1]; tf32split(e, h4.y, l4.y);
            e = __expf(v.z + ca - AUX[q4 + 2]) * AUX[128 + q4 + 2]; tf32split(e, h4.z, l4.z);
            e = __expf(v.w + ca - AUX[q4 + 3]) * AUX[128 + q4 + 3]; tf32split(e, h4.w, l4.w);
            *(float4*)(AH + kk * TSTR + q4) = h4;
            *(float4*)(AL + kk * TSTR + q4) = l4;
            // B: C[d][c] transposed (k=c)
            int drow = (tid >> 3) + p * 32;
            int cc = (tid & 7) * 4;
            float4 w = *(const float4*)(Cb + (size_t)drow * LC + c0chunk + k0 + cc);
            float h, l;
            tf32split(w.x, h, l); BH[(cc + 0) * TSTR + drow] = h; BL[(cc + 0) * TSTR + drow] = l;
            tf32split(w.y, h, l); BH[(cc + 1) * TSTR + drow] = h; BL[(cc + 1) * TSTR + drow] = l;
            tf32split(w.z, h, l); BH[(cc + 2) * TSTR + drow] = h; BL[(cc + 2) * TSTR + drow] = l;
            tf32split(w.w, h, l); BH[(cc + 3) * TSTR + drow] = h; BL[(cc + 3) * TSTR + drow] = l;
        }
        __syncthreads();
        mma_chunk(AH, AL, BH, BL, acc, mbase, nbase, lane);
        __syncthreads();
    }

    int lq = lane >> 2, kq = lane & 3;
    float* Vp = g_V2p + ((size_t)part * BB * LQ + (size_t)b * LQ + qb) * DD;
    #pragma unroll
    for (int ma = 0; ma < 2; ma++)
        #pragma unroll
        for (int na = 0; na < 8; na++) {
            int r = mbase + 16 * ma + lq;
            int col = nbase + 8 * na + kq * 2;
            *(float2*)(Vp + (size_t)r * DD + col) =
                make_float2(acc[ma][na][0], acc[ma][na][1]);
            *(float2*)(Vp + (size_t)(r + 8) * DD + col) =
                make_float2(acc[ma][na][2], acc[ma][na][3]);
        }
}

__global__ void k_reduceV2() {
    const int n = BB * LQ * DD / 4;
    int i = blockIdx.x * blockDim.x + threadIdx.x;
    if (i < n) {
        const float4* p = (const float4*)g_V2p;
        float4 a = p[i], b2 = p[i + n], c = p[i + 2 * n], d = p[i + 3 * n];
        float4 o;
        o.x = a.x + b2.x + c.x + d.x;
        o.y = a.y + b2.y + c.y + d.y;
        o.z = a.z + b2.z + c.z + d.z;
        o.w = a.w + b2.w + c.w + d.w;
        ((float4*)g_V2)[i] = o;
    }
}

// ============================================================
// K5: Bmat = S1 @ V2  [m=c, n=d, k=q(512)]
// ============================================================
__global__ __launch_bounds__(256, 2) void k_gemmB(const int* __restrict__ Qmask) {
    extern __shared__ float smf[];
    float* AH = smf;
    float* AL = AH + TILE_F;
    float* BH = AL + TILE_F;
    float* BL = BH + TILE_F;
    float* AUX = BL + TILE_F;
    int tid = threadIdx.x, wid = tid >> 5, lane = tid & 31;
    int b = blockIdx.y, cb = blockIdx.x * 128;
    int mbase = (wid >> 1) * 32, nbase = (wid & 1) * 64;

    if (tid < 128) {
        AUX[tid] = g_rmax[b * LC + cb + tid];
        AUX[128 + tid] = g_rinv[b * LC + cb + tid];
    }
    for (int i = tid; i < 512; i += 256) AUX[256 + i] = Qmask[b * LQ + i] ? 0.f : NEGF;
    __syncthreads();

    float acc[2][8][4];
    #pragma unroll
    for (int i = 0; i < 2; i++)
        #pragma unroll
        for (int j = 0; j < 8; j++)
            #pragma unroll
            for (int r = 0; r < 4; r++) acc[i][j][r] = 0.f;

    const float* Sb = g_S + ((size_t)b * LC + cb) * LQ;
    const float* Vb = g_V2 + (size_t)b * LQ * DD;

    for (int k0 = 0; k0 < LQ; k0 += 32) {
        #pragma unroll
        for (int p = 0; p < 4; p++) {
            int row = (tid >> 3) + p * 32;
            int qq = (tid & 7) * 4;
            float4 v = *(const float4*)(Sb + (size_t)row * LQ + k0 + qq);
            float rm = AUX[row], ri = AUX[128 + row];
            float h, l, e;
            e = __expf(v.x + AUX[256 + k0 + qq + 0] - rm) * ri; tf32split(e, h, l);
            AH[(qq + 0) * TSTR + row] = h; AL[(qq + 0) * TSTR + row] = l;
            e = __expf(v.y + AUX[256 + k0 + qq + 1] - rm) * ri; tf32split(e, h, l);
            AH[(qq + 1) * TSTR + row] = h; AL[(qq + 1) * TSTR + row] = l;
            e = __expf(v.z + AUX[256 + k0 + qq + 2] - rm) * ri; tf32split(e, h, l);
            AH[(qq + 2) * TSTR + row] = h; AL[(qq + 2) * TSTR + row] = l;
            e = __expf(v.w + AUX[256 + k0 + qq + 3] - rm) * ri; tf32split(e, h, l);
            AH[(qq + 3) * TSTR + row] = h; AL[(qq + 3) * TSTR + row] = l;
            // B: V2[q][d] direct rows (k=q)
            int kk = (tid >> 5) + p * 8;
            int d4 = (tid & 31) * 4;
            float4 w = *(const float4*)(Vb + (size_t)(k0 + kk) * DD + d4);
            float4 h4, l4;
            tf32split(w.x, h4.x, l4.x); tf32split(w.y, h4.y, l4.y);
            tf32split(w.z, h4.z, l4.z); tf32split(w.w, h4.w, l4.w);
            *(float4*)(BH + kk * TSTR + d4) = h4;
            *(float4*)(BL + kk * TSTR + d4) = l4;
        }
        __syncthreads();
        mma_chunk(AH, AL, BH, BL, acc, mbase, nbase, lane);
        __syncthreads();
    }

    int lq = lane >> 2, kq = lane & 3;
    float* Bmb = g_Bm + ((size_t)b * LC + cb) * DD;
    #pragma unroll
    for (int ma = 0; ma < 2; ma++)
        #pragma unroll
        for (int na = 0; na < 8; na++) {
            int r = mbase + 16 * ma + lq;
            int col = nbase + 8 * na + kq * 2;
            *(float2*)(Bmb + (size_t)r * DD + col) =
                make_float2(acc[ma][na][0], acc[ma][na][1]);
            *(float2*)(Bmb + (size_t)(r + 8) * DD + col) =
                make_float2(acc[ma][na][2], acc[ma][na][3]);
        }
}

// ============================================================
// K6: assemble
// ============================================================
__global__ void k_assemble(const float* __restrict__ C, float* __restrict__ out) {
    __shared__ float As[32][33], Bs[32][33];
    int b = blockIdx.z, cb = blockIdx.x * 32, db = blockIdx.y * 32;
    int x = threadIdx.x, y = threadIdx.y;
    #pragma unroll
    for (int yy = 0; yy < 4; yy++) {
        int c = y + 8 * yy;
        As[c][x] = g_A[((size_t)b * LC + cb + c) * DD + db + x];
        Bs[c][x] = g_Bm[((size_t)b * LC + cb + c) * DD + db + x];
    }
    __syncthreads();
    #pragma unroll
    for (int yy = 0; yy < 4; yy++) {
        int d = y + 8 * yy;
        float cv = C[((size_t)b * DD + db + d) * LC + cb + x];
        float av = As[x][d], bv = Bs[x][d];
        size_t o = (size_t)b * 4 * DD * LC + cb + x;
        out[o + (size_t)(db + d) * LC] = cv;
        out[o + (size_t)(DD + db + d) * LC] = av;
        out[o + (size_t)(2 * DD + db + d) * LC] = cv * av;
        out[o + (size_t)(3 * DD + db + d) * LC] = cv * bv;
    }
}

extern "C" void kernel_launch(void* const* d_in, const int* in_sizes, int n_in,
                              void* d_out, int out_size) {
    const float* C = (const float*)d_in[0];
    const float* Q = (const float*)d_in[1];
    const int* Cmask = (const int*)d_in[2];
    const int* Qmask = (const int*)d_in[3];
    const float* w4C = (const float*)d_in[4];
    const float* w4Q = (const float*)d_in[5];
    const float* w4mlu = (const float*)d_in[6];
    const float* bias = (const float*)d_in[7];
    float* out = (float*)d_out;

    cudaFuncSetAttribute(k_scores, cudaFuncAttributeMaxDynamicSharedMemorySize, SMEM_BYTES);
    cudaFuncSetAttribute(k_gemmA, cudaFuncAttributeMaxDynamicSharedMemorySize, SMEM_BYTES);
    cudaFuncSetAttribute(k_gemmV2, cudaFuncAttributeMaxDynamicSharedMemorySize, SMEM_BYTES);
    cudaFuncSetAttribute(k_gemmB, cudaFuncAttributeMaxDynamicSharedMemorySize, SMEM_BYTES);

    int nsub = BB * LC + BB * LQ;
    k_sub<<<(nsub + 255) / 256, 256>>>(C, Q, w4C, w4Q, bias);
    k_scores<<<dim3(4, 16, 16), 256, SMEM_BYTES>>>(C, Q, w4mlu);
    k_rowstats<<<(BB * LC) / 8, 256>>>(Qmask);
    k_colstats_part<<<dim3(16, 4, 16), 256>>>(Cmask);
    k_colstats_merge<<<32, 256>>>();
    k_gemmA<<<dim3(16, 16), 256, SMEM_BYTES>>>(Q, Qmask);
    k_gemmV2<<<dim3(4, 4, 16), 256, SMEM_BYTES>>>(C, Cmask);
    k_reduceV2<<<(BB * LQ * DD / 4 + 255) / 256, 256>>>();
    k_gemmB<<<dim3(16, 16), 256, SMEM_BYTES>>>(Qmask);
    k_assemble<<<dim3(64, 4, 16), dim3(32, 8)>>>(C, out);
}

// round 6
// speedup vs baseline: 1.1521x; 1.1521x over previous
#include <cuda_runtime.h>
#include <cuda_bf16.h>
#include <math.h>
#include <stdint.h>

#define BB 16
#define DD 128
#define LC 2048
#define LQ 512
#define NEGF (-1e30f)

// ---- scratch ----
__device__ float g_S[(size_t)BB * LC * LQ];
__device__ float g_A[(size_t)BB * LC * DD];
__device__ float g_Bm[(size_t)BB * LC * DD];
__device__ float g_V2[(size_t)BB * LQ * DD];
__device__ float g_V2p[(size_t)4 * BB * LQ * DD];
__device__ float g_sub0[BB * LC];
__device__ float g_sub1[BB * LQ];
__device__ float g_rmax[BB * LC], g_rinv[BB * LC];
__device__ float g_cmax[BB * LQ], g_cinv[BB * LQ];
__device__ float g_cpm[4 * BB * LQ], g_cps[4 * BB * LQ];

// smem: 4 packed-bf16x2 tiles uint32[16][TSTR2] + AUX floats[768]
#define TSTR2 136
#define TILE_U (16 * TSTR2)
#define SMEM_BYTES ((4 * TILE_U + 768) * 4)

__device__ __forceinline__ void split2(float v0, float v1, uint32_t& H, uint32_t& L) {
    __nv_bfloat16 h0 = __float2bfloat16(v0), h1 = __float2bfloat16(v1);
    float r0 = v0 - __bfloat162float(h0), r1 = v1 - __bfloat162float(h1);
    H = (uint32_t)__bfloat16_as_ushort(h0) | ((uint32_t)__bfloat16_as_ushort(h1) << 16);
    __nv_bfloat16 l0 = __float2bfloat16(r0), l1 = __float2bfloat16(r1);
    L = (uint32_t)__bfloat16_as_ushort(l0) | ((uint32_t)__bfloat16_as_ushort(l1) << 16);
}

#define MMA16(c, a, b0, b1)                                                   \
    asm volatile(                                                             \
        "mma.sync.aligned.m16n8k16.row.col.f32.bf16.bf16.f32 "                \
        "{%0,%1,%2,%3}, {%4,%5,%6,%7}, {%8,%9}, {%0,%1,%2,%3};"               \
        : "+f"((c)[0]), "+f"((c)[1]), "+f"((c)[2]), "+f"((c)[3])              \
        : "r"((a)[0]), "r"((a)[1]), "r"((a)[2]), "r"((a)[3]),                 \
          "r"(b0), "r"(b1))

// one BK=32 chunk; warp tile 32(m) x 64(n); tiles are [kpair][row] uint32
__device__ __forceinline__ void mma_chunk(const uint32_t* AH, const uint32_t* AL,
                                          const uint32_t* BH, const uint32_t* BL,
                                          float acc[2][8][4],
                                          int mbase, int nbase, int lane) {
    int lq = lane >> 2, kq = lane & 3;
    #pragma unroll
    for (int s = 0; s < 2; s++) {
        int kb = s * 8;
        uint32_t ah[2][4], al[2][4];
        #pragma unroll
        for (int ma = 0; ma < 2; ma++) {
            int r = mbase + 16 * ma + lq;
            ah[ma][0] = AH[(kb + kq) * TSTR2 + r];
            ah[ma][1] = AH[(kb + kq) * TSTR2 + r + 8];
            ah[ma][2] = AH[(kb + kq + 4) * TSTR2 + r];
            ah[ma][3] = AH[(kb + kq + 4) * TSTR2 + r + 8];
            al[ma][0] = AL[(kb + kq) * TSTR2 + r];
            al[ma][1] = AL[(kb + kq) * TSTR2 + r + 8];
            al[ma][2] = AL[(kb + kq + 4) * TSTR2 + r];
            al[ma][3] = AL[(kb + kq + 4) * TSTR2 + r + 8];
        }
        #pragma unroll
        for (int na = 0; na < 8; na++) {
            int c0 = nbase + 8 * na + lq;
            uint32_t bh0 = BH[(kb + kq) * TSTR2 + c0];
            uint32_t bh1 = BH[(kb + kq + 4) * TSTR2 + c0];
            uint32_t bl0 = BL[(kb + kq) * TSTR2 + c0];
            uint32_t bl1 = BL[(kb + kq + 4) * TSTR2 + c0];
            #pragma unroll
            for (int ma = 0; ma < 2; ma++) {
                MMA16(acc[ma][na], ah[ma], bh0, bh1);
                MMA16(acc[ma][na], ah[ma], bl0, bl1);
                MMA16(acc[ma][na], al[ma], bh0, bh1);
            }
        }
    }
}

// ============================================================
// K0: sub0 / sub1
// ============================================================
__global__ void k_sub(const float* __restrict__ C, const float* __restrict__ Q,
                      const float* __restrict__ w4C, const float* __restrict__ w4Q,
                      const float* __restrict__ bias) {
    int t = blockIdx.x * blockDim.x + threadIdx.x;
    const int totC = BB * LC;
    if (t < totC) {
        int b = t / LC, c = t % LC;
        const float* Cp = C + (size_t)b * DD * LC + c;
        float s = 0.f;
        #pragma unroll 8
        for (int d = 0; d < DD; d++) s += Cp[(size_t)d * LC] * w4C[d];
        g_sub0[t] = s;
    } else if (t < totC + BB * LQ) {
        int u = t - totC;
        int b = u / LQ, q = u % LQ;
        const float* Qp = Q + (size_t)b * DD * LQ + q;
        float s = bias[0];
        #pragma unroll 8
        for (int d = 0; d < DD; d++) s += Qp[(size_t)d * LQ] * w4Q[d];
        g_sub1[u] = s;
    }
}

// ============================================================
// K1: S = (C*w)^T Q + sub0 + sub1  [m=c, n=q, k=d(128)]
// ============================================================
__global__ __launch_bounds__(256, 2) void k_scores(const float* __restrict__ C,
                                                   const float* __restrict__ Q,
                                                   const float* __restrict__ w4mlu) {
    extern __shared__ uint32_t smu[];
    uint32_t* TAH = smu;
    uint32_t* TAL = TAH + TILE_U;
    uint32_t* TBH = TAL + TILE_U;
    uint32_t* TBL = TBH + TILE_U;
    float* AUX = (float*)(TBL + TILE_U);
    int tid = threadIdx.x, wid = tid >> 5, lane = tid & 31;
    int b = blockIdx.z, cb = blockIdx.y * 128, qb = blockIdx.x * 128;
    int mbase = (wid >> 1) * 32, nbase = (wid & 1) * 64;
    const float* Cb = C + (size_t)b * DD * LC + cb;
    const float* Qb = Q + (size_t)b * DD * LQ + qb;

    if (tid < 128) {
        AUX[tid] = g_sub0[b * LC + cb + tid];
        AUX[128 + tid] = g_sub1[b * LQ + qb + tid];
    }

    float acc[2][8][4];
    #pragma unroll
    for (int i = 0; i < 2; i++)
        #pragma unroll
        for (int j = 0; j < 8; j++)
            #pragma unroll
            for (int r = 0; r < 4; r++) acc[i][j][r] = 0.f;

    for (int k0 = 0; k0 < DD; k0 += 32) {
        // pattern T for both A (C*w, k=d rows) and B (Q, k=d rows)
        #pragma unroll
        for (int it = 0; it < 4; it++) {
            int idx = tid + it * 256;          // 0..1023
            int kp = idx & 15, cp = idx >> 4;  // kpair, col-pair
            int c2 = cp * 2;
            int d0 = k0 + 2 * kp;
            float w0 = w4mlu[d0], w1 = w4mlu[d0 + 1];
            float2 a0 = *(const float2*)(Cb + (size_t)d0 * LC + c2);
            float2 a1 = *(const float2*)(Cb + (size_t)(d0 + 1) * LC + c2);
            uint32_t H, L;
            split2(a0.x * w0, a1.x * w1, H, L);
            TAH[kp * TSTR2 + c2] = H; TAL[kp * TSTR2 + c2] = L;
            split2(a0.y * w0, a1.y * w1, H, L);
            TAH[kp * TSTR2 + c2 + 1] = H; TAL[kp * TSTR2 + c2 + 1] = L;
            float2 q0 = *(const float2*)(Qb + (size_t)d0 * LQ + c2);
            float2 q1 = *(const float2*)(Qb + (size_t)(d0 + 1) * LQ + c2);
            split2(q0.x, q1.x, H, L);
            TBH[kp * TSTR2 + c2] = H; TBL[kp * TSTR2 + c2] = L;
            split2(q0.y, q1.y, H, L);
            TBH[kp * TSTR2 + c2 + 1] = H; TBL[kp * TSTR2 + c2 + 1] = L;
        }
        __syncthreads();
        mma_chunk(TAH, TAL, TBH, TBL, acc, mbase, nbase, lane);
        __syncthreads();
    }

    int lq = lane >> 2, kq = lane & 3;
    #pragma unroll
    for (int ma = 0; ma < 2; ma++)
        #pragma unroll
        for (int na = 0; na < 8; na++) {
            int r = mbase + 16 * ma + lq;
            int col = nbase + 8 * na + kq * 2;
            float s1a = AUX[128 + col], s1b = AUX[128 + col + 1];
            float s0a = AUX[r], s0b = AUX[r + 8];
            float* o0 = g_S + ((size_t)b * LC + cb + r) * LQ + qb + col;
            float* o1 = g_S + ((size_t)b * LC + cb + r + 8) * LQ + qb + col;
            *(float2*)o0 = make_float2(acc[ma][na][0] + s0a + s1a,
                                       acc[ma][na][1] + s0a + s1b);
            *(float2*)o1 = make_float2(acc[ma][na][2] + s0b + s1a,
                                       acc[ma][na][3] + s0b + s1b);
        }
}

// ============================================================
// stats
// ============================================================
__global__ void k_rowstats(const int* __restrict__ Qmask) {
    int w = blockIdx.x * 8 + (threadIdx.x >> 5);
    int lane = threadIdx.x & 31;
    if (w >= BB * LC) return;
    int b = w / LC;
    const float* Sp = g_S + (size_t)w * LQ;
    const int* qm = Qmask + b * LQ;
    float vals[16], m = -INFINITY;
    #pragma unroll
    for (int i = 0; i < 16; i++) {
        int q = lane + 32 * i;
        float v = Sp[q];
        if (!qm[q]) v += NEGF;
        vals[i] = v; m = fmaxf(m, v);
    }
    #pragma unroll
    for (int o = 16; o > 0; o >>= 1) m = fmaxf(m, __shfl_xor_sync(~0u, m, o));
    float s = 0.f;
    #pragma unroll
    for (int i = 0; i < 16; i++) s += __expf(vals[i] - m);
    #pragma unroll
    for (int o = 16; o > 0; o >>= 1) s += __shfl_xor_sync(~0u, s, o);
    if (lane == 0) { g_rmax[w] = m; g_rinv[w] = 1.f / s; }
}

__global__ void k_colstats_part(const int* __restrict__ Cmask) {
    __shared__ float sm[8][33], ss[8][33];
    __shared__ float cadd[512];
    int b = blockIdx.z, chunk = blockIdx.y * 512;
    int lane = threadIdx.x & 31, yg = threadIdx.x >> 5;
    for (int i = threadIdx.x; i < 512; i += 256)
        cadd[i] = Cmask[b * LC + chunk + i] ? 0.f : NEGF;
    __syncthreads();
    int q = blockIdx.x * 32 + lane, cl = yg * 64;
    const float* Sp = g_S + (size_t)b * LC * LQ + (size_t)(chunk + cl) * LQ + q;
    float m = -INFINITY, s = 0.f;
    #pragma unroll 4
    for (int i = 0; i < 16; i++) {
        const float* p = Sp + (size_t)i * 4 * LQ;
        float v0 = p[0] + cadd[cl + i * 4], v1 = p[LQ] + cadd[cl + i * 4 + 1];
        float v2 = p[2 * LQ] + cadd[cl + i * 4 + 2], v3 = p[3 * LQ] + cadd[cl + i * 4 + 3];
        float mn = fmaxf(m, fmaxf(fmaxf(v0, v1), fmaxf(v2, v3)));
        s = s * __expf(m - mn) + __expf(v0 - mn) + __expf(v1 - mn)
                               + __expf(v2 - mn) + __expf(v3 - mn);
        m = mn;
    }
    sm[yg][lane] = m; ss[yg][lane] = s;
    __syncthreads();
    if (yg == 0) {
        float M = m, S = s;
        #pragma unroll
        for (int g = 1; g < 8; g++) {
            float m2 = sm[g][lane], s2 = ss[g][lane], mn = fmaxf(M, m2);
            S = S * __expf(M - mn) + s2 * __expf(m2 - mn); M = mn;
        }
        int idx = (blockIdx.y * BB + b) * LQ + q;
        g_cpm[idx] = M; g_cps[idx] = S;
    }
}

__global__ void k_colstats_merge() {
    int t = blockIdx.x * 256 + threadIdx.x;
    if (t >= BB * LQ) return;
    float M = -INFINITY, S = 0.f;
    #pragma unroll
    for (int g = 0; g < 4; g++) {
        float m2 = g_cpm[g * BB * LQ + t], s2 = g_cps[g * BB * LQ + t], mn = fmaxf(M, m2);
        S = S * __expf(M - mn) + s2 * __expf(m2 - mn); M = mn;
    }
    g_cmax[t] = M; g_cinv[t] = 1.f / S;
}

// ============================================================
// K3: A = S1 @ Qt  [m=c, n=d, k=q(512)]  A:R, B:R
// ============================================================
__global__ __launch_bounds__(256, 2) void k_gemmA(const float* __restrict__ Q,
                                                  const int* __restrict__ Qmask) {
    extern __shared__ uint32_t smu[];
    uint32_t* TAH = smu;
    uint32_t* TAL = TAH + TILE_U;
    uint32_t* TBH = TAL + TILE_U;
    uint32_t* TBL = TBH + TILE_U;
    float* AUX = (float*)(TBL + TILE_U);
    int tid = threadIdx.x, wid = tid >> 5, lane = tid & 31;
    int b = blockIdx.y, cb = blockIdx.x * 128;
    int mbase = (wid >> 1) * 32, nbase = (wid & 1) * 64;

    if (tid < 128) {
        AUX[tid] = g_rmax[b * LC + cb + tid];
        AUX[128 + tid] = g_rinv[b * LC + cb + tid];
    }
    for (int i = tid; i < 512; i += 256) AUX[256 + i] = Qmask[b * LQ + i] ? 0.f : NEGF;
    __syncthreads();

    float acc[2][8][4];
    #pragma unroll
    for (int i = 0; i < 2; i++)
        #pragma unroll
        for (int j = 0; j < 8; j++)
            #pragma unroll
            for (int r = 0; r < 4; r++) acc[i][j][r] = 0.f;

    const float* Qb = Q + (size_t)b * DD * LQ;
    const float* Sb = g_S + ((size_t)b * LC + cb) * LQ;

    for (int k0 = 0; k0 < LQ; k0 += 32) {
        #pragma unroll
        for (int p = 0; p < 4; p++) {
            int row = (tid >> 3) + p * 32;
            int qq = (tid & 7) * 4;
            int kp = (tid & 7) * 2;
            // A: exp(S1) row=c, k=q contiguous
            float4 v = *(const float4*)(Sb + (size_t)row * LQ + k0 + qq);
            float rm = AUX[row], ri = AUX[128 + row];
            float e0 = __expf(v.x + AUX[256 + k0 + qq + 0] - rm) * ri;
            float e1 = __expf(v.y + AUX[256 + k0 + qq + 1] - rm) * ri;
            float e2 = __expf(v.z + AUX[256 + k0 + qq + 2] - rm) * ri;
            float e3 = __expf(v.w + AUX[256 + k0 + qq + 3] - rm) * ri;
            uint32_t H, L;
            split2(e0, e1, H, L);
            TAH[kp * TSTR2 + row] = H; TAL[kp * TSTR2 + row] = L;
            split2(e2, e3, H, L);
            TAH[(kp + 1) * TSTR2 + row] = H; TAL[(kp + 1) * TSTR2 + row] = L;
            // B: Q row=d (n), k=q contiguous
            float4 w = *(const float4*)(Qb + (size_t)row * LQ + k0 + qq);
            split2(w.x, w.y, H, L);
            TBH[kp * TSTR2 + row] = H; TBL[kp * TSTR2 + row] = L;
            split2(w.z, w.w, H, L);
            TBH[(kp + 1) * TSTR2 + row] = H; TBL[(kp + 1) * TSTR2 + row] = L;
        }
        __syncthreads();
        mma_chunk(TAH, TAL, TBH, TBL, acc, mbase, nbase, lane);
        __syncthreads();
    }

    int lq = lane >> 2, kq = lane & 3;
    float* Ab = g_A + ((size_t)b * LC + cb) * DD;
    #pragma unroll
    for (int ma = 0; ma < 2; ma++)
        #pragma unroll
        for (int na = 0; na < 8; na++) {
            int r = mbase + 16 * ma + lq;
            int col = nbase + 8 * na + kq * 2;
            *(float2*)(Ab + (size_t)r * DD + col) =
                make_float2(acc[ma][na][0], acc[ma][na][1]);
            *(float2*)(Ab + (size_t)(r + 8) * DD + col) =
                make_float2(acc[ma][na][2], acc[ma][na][3]);
        }
}

// ============================================================
// K4: V2 partials [m=q, n=d, k=c]  A:T (exp S2), B:R (C)
// ============================================================
__global__ __launch_bounds__(256, 2) void k_gemmV2(const float* __restrict__ C,
                                                   const int* __restrict__ Cmask) {
    extern __shared__ uint32_t smu[];
    uint32_t* TAH = smu;
    uint32_t* TAL = TAH + TILE_U;
    uint32_t* TBH = TAL + TILE_U;
    uint32_t* TBL = TBH + TILE_U;
    float* AUX = (float*)(TBL + TILE_U);
    int tid = threadIdx.x, wid = tid >> 5, lane = tid & 31;
    int b = blockIdx.z, part = blockIdx.y, qb = blockIdx.x * 128;
    int mbase = (wid >> 1) * 32, nbase = (wid & 1) * 64;
    int c0chunk = part * 512;

    if (tid < 128) {
        AUX[tid] = g_cmax[b * LQ + qb + tid];
        AUX[128 + tid] = g_cinv[b * LQ + qb + tid];
    }
    for (int i = tid; i < 512; i += 256) AUX[256 + i] = Cmask[b * LC + c0chunk + i] ? 0.f : NEGF;
    __syncthreads();

    float acc[2][8][4];
    #pragma unroll
    for (int i = 0; i < 2; i++)
        #pragma unroll
        for (int j = 0; j < 8; j++)
            #pragma unroll
            for (int r = 0; r < 4; r++) acc[i][j][r] = 0.f;

    const float* Cb = C + (size_t)b * DD * LC;
    const float* Sb = g_S + ((size_t)b * LC + c0chunk) * LQ + qb;

    for (int k0 = 0; k0 < 512; k0 += 32) {
        // A: pattern T over S2 rows (k=c)
        #pragma unroll
        for (int it = 0; it < 4; it++) {
            int idx = tid + it * 256;
            int kp = idx & 15, qp = idx >> 4;
            int q2 = qp * 2;
            int cg = k0 + 2 * kp;
            float2 v0 = *(const float2*)(Sb + (size_t)cg * LQ + q2);
            float2 v1 = *(const float2*)(Sb + (size_t)(cg + 1) * LQ + q2);
            float ca0 = AUX[256 + cg - k0 + k0], ca1 = AUX[256 + cg + 1 - k0 + k0];
            float e00 = __expf(v0.x + ca0 - AUX[q2]) * AUX[128 + q2];
            float e10 = __expf(v1.x + ca1 - AUX[q2]) * AUX[128 + q2];
            float e01 = __expf(v0.y + ca0 - AUX[q2 + 1]) * AUX[128 + q2 + 1];
            float e11 = __expf(v1.y + ca1 - AUX[q2 + 1]) * AUX[128 + q2 + 1];
            uint32_t H, L;
            split2(e00, e10, H, L);
            TAH[kp * TSTR2 + q2] = H; TAL[kp * TSTR2 + q2] = L;
            split2(e01, e11, H, L);
            TAH[kp * TSTR2 + q2 + 1] = H; TAL[kp * TSTR2 + q2 + 1] = L;
        }
        // B: pattern R over C rows d, k=c contiguous
        #pragma unroll
        for (int p = 0; p < 4; p++) {
            int row = (tid >> 3) + p * 32;
            int cc = (tid & 7) * 4;
            int kp = (tid & 7) * 2;
            float4 w = *(const float4*)(Cb + (size_t)row * LC + c0chunk + k0 + cc);
            uint32_t H, L;
            split2(w.x, w.y, H, L);
            TBH[kp * TSTR2 + row] = H; TBL[kp * TSTR2 + row] = L;
            split2(w.z, w.w, H, L);
            TBH[(kp + 1) * TSTR2 + row] = H; TBL[(kp + 1) * TSTR2 + row] = L;
        }
        __syncthreads();
        mma_chunk(TAH, TAL, TBH, TBL, acc, mbase, nbase, lane);
        __syncthreads();
    }

    int lq = lane >> 2, kq = lane & 3;
    float* Vp = g_V2p + ((size_t)part * BB * LQ + (size_t)b * LQ + qb) * DD;
    #pragma unroll
    for (int ma = 0; ma < 2; ma++)
        #pragma unroll
        for (int na = 0; na < 8; na++) {
            int r = mbase + 16 * ma + lq;
            int col = nbase + 8 * na + kq * 2;
            *(float2*)(Vp + (size_t)r * DD + col) =
                make_float2(acc[ma][na][0], acc[ma][na][1]);
            *(float2*)(Vp + (size_t)(r + 8) * DD + col) =
                make_float2(acc[ma][na][2], acc[ma][na][3]);
        }
}

__global__ void k_reduceV2() {
    const int n = BB * LQ * DD / 4;
    int i = blockIdx.x * blockDim.x + threadIdx.x;
    if (i < n) {
        const float4* p = (const float4*)g_V2p;
        float4 a = p[i], b2 = p[i + n], c = p[i + 2 * n], d = p[i + 3 * n];
        float4 o;
        o.x = a.x + b2.x + c.x + d.x;
        o.y = a.y + b2.y + c.y + d.y;
        o.z = a.z + b2.z + c.z + d.z;
        o.w = a.w + b2.w + c.w + d.w;
        ((float4*)g_V2)[i] = o;
    }
}

// ============================================================
// K5: Bmat = S1 @ V2  [m=c, n=d, k=q(512)]  A:R, B:T (V2[q][d])
// ============================================================
__global__ __launch_bounds__(256, 2) void k_gemmB(const int* __restrict__ Qmask) {
    extern __shared__ uint32_t smu[];
    uint32_t* TAH = smu;
    uint32_t* TAL = TAH + TILE_U;
    uint32_t* TBH = TAL + TILE_U;
    uint32_t* TBL = TBH + TILE_U;
    float* AUX = (float*)(TBL + TILE_U);
    int tid = threadIdx.x, wid = tid >> 5, lane = tid & 31;
    int b = blockIdx.y, cb = blockIdx.x * 128;
    int mbase = (wid >> 1) * 32, nbase = (wid & 1) * 64;

    if (tid < 128) {
        AUX[tid] = g_rmax[b * LC + cb + tid];
        AUX[128 + tid] = g_rinv[b * LC + cb + tid];
    }
    for (int i = tid; i < 512; i += 256) AUX[256 + i] = Qmask[b * LQ + i] ? 0.f : NEGF;
    __syncthreads();

    float acc[2][8][4];
    #pragma unroll
    for (int i = 0; i < 2; i++)
        #pragma unroll
        for (int j = 0; j < 8; j++)
            #pragma unroll
            for (int r = 0; r < 4; r++) acc[i][j][r] = 0.f;

    const float* Sb = g_S + ((size_t)b * LC + cb) * LQ;
    const float* Vb = g_V2 + (size_t)b * LQ * DD;

    for (int k0 = 0; k0 < LQ; k0 += 32) {
        // A: pattern R (exp S1)
        #pragma unroll
        for (int p = 0; p < 4; p++) {
            int row = (tid >> 3) + p * 32;
            int qq = (tid & 7) * 4;
            int kp = (tid & 7) * 2;
            float4 v = *(const float4*)(Sb + (size_t)row * LQ + k0 + qq);
            float rm = AUX[row], ri = AUX[128 + row];
            float e0 = __expf(v.x + AUX[256 + k0 + qq + 0] - rm) * ri;
            float e1 = __expf(v.y + AUX[256 + k0 + qq + 1] - rm) * ri;
            float e2 = __expf(v.z + AUX[256 + k0 + qq + 2] - rm) * ri;
            float e3 = __expf(v.w + AUX[256 + k0 + qq + 3] - rm) * ri;
            uint32_t H, L;
            split2(e0, e1, H, L);
            TAH[kp * TSTR2 + row] = H; TAL[kp * TSTR2 + row] = L;
            split2(e2, e3, H, L);
            TAH[(kp + 1) * TSTR2 + row] = H; TAL[(kp + 1) * TSTR2 + row] = L;
        }
        // B: pattern T over V2[q][d]
        #pragma unroll
        for (int it = 0; it < 2; it++) {
            int idx = tid + it * 256;          // 0..511: 16 kp x 32? need 16 kp x 64 dpair = 1024
            int kp = idx & 15, dp = idx >> 4;  // dp 0..31 => handles d2 = dp*4? adjust below
            // handle two d-pairs per thread to cover 64 pairs with 512 iters
            int d2 = dp * 4;
            int qg = k0 + 2 * kp;
            float4 v0 = *(const float4*)(Vb + (size_t)qg * DD + d2);
            float4 v1 = *(const float4*)(Vb + (size_t)(qg + 1) * DD + d2);
            uint32_t H, L;
            split2(v0.x, v1.x, H, L);
            TBH[kp * TSTR2 + d2] = H; TBL[kp * TSTR2 + d2] = L;
            split2(v0.y, v1.y, H, L);
            TBH[kp * TSTR2 + d2 + 1] = H; TBL[kp * TSTR2 + d2 + 1] = L;
            split2(v0.z, v1.z, H, L);
            TBH[kp * TSTR2 + d2 + 2] = H; TBL[kp * TSTR2 + d2 + 2] = L;
            split2(v0.w, v1.w, H, L);
            TBH[kp * TSTR2 + d2 + 3] = H; TBL[kp * TSTR2 + d2 + 3] = L;
        }
        __syncthreads();
        mma_chunk(TAH, TAL, TBH, TBL, acc, mbase, nbase, lane);
        __syncthreads();
    }

    int lq = lane >> 2, kq = lane & 3;
    float* Bmb = g_Bm + ((size_t)b * LC + cb) * DD;
    #pragma unroll
    for (int ma = 0; ma < 2; ma++)
        #pragma unroll
        for (int na = 0; na < 8; na++) {
            int r = mbase + 16 * ma + lq;
            int col = nbase + 8 * na + kq * 2;
            *(float2*)(Bmb + (size_t)r * DD + col) =
                make_float2(acc[ma][na][0], acc[ma][na][1]);
            *(float2*)(Bmb + (size_t)(r + 8) * DD + col) =
                make_float2(acc[ma][na][2], acc[ma][na][3]);
        }
}

// ============================================================
// K6: assemble
// ============================================================
__global__ void k_assemble(const float* __restrict__ C, float* __restrict__ out) {
    __shared__ float As[32][33], Bs[32][33];
    int b = blockIdx.z, cb = blockIdx.x * 32, db = blockIdx.y * 32;
    int x = threadIdx.x, y = threadIdx.y;
    #pragma unroll
    for (int yy = 0; yy < 4; yy++) {
        int c = y + 8 * yy;
        As[c][x] = g_A[((size_t)b * LC + cb + c) * DD + db + x];
        Bs[c][x] = g_Bm[((size_t)b * LC + cb + c) * DD + db + x];
    }
    __syncthreads();
    #pragma unroll
    for (int yy = 0; yy < 4; yy++) {
        int d = y + 8 * yy;
        float cv = C[((size_t)b * DD + db + d) * LC + cb + x];
        float av = As[x][d], bv = Bs[x][d];
        size_t o = (size_t)b * 4 * DD * LC + cb + x;
        out[o + (size_t)(db + d) * LC] = cv;
        out[o + (size_t)(DD + db + d) * LC] = av;
        out[o + (size_t)(2 * DD + db + d) * LC] = cv * av;
        out[o + (size_t)(3 * DD + db + d) * LC] = cv * bv;
    }
}

extern "C" void kernel_launch(void* const* d_in, const int* in_sizes, int n_in,
                              void* d_out, int out_size) {
    const float* C = (const float*)d_in[0];
    const float* Q = (const float*)d_in[1];
    const int* Cmask = (const int*)d_in[2];
    const int* Qmask = (const int*)d_in[3];
    const float* w4C = (const float*)d_in[4];
    const float* w4Q = (const float*)d_in[5];
    const float* w4mlu = (const float*)d_in[6];
    const float* bias = (const float*)d_in[7];
    float* out = (float*)d_out;

    cudaFuncSetAttribute(k_scores, cudaFuncAttributeMaxDynamicSharedMemorySize, SMEM_BYTES);
    cudaFuncSetAttribute(k_gemmA, cudaFuncAttributeMaxDynamicSharedMemorySize, SMEM_BYTES);
    cudaFuncSetAttribute(k_gemmV2, cudaFuncAttributeMaxDynamicSharedMemorySize, SMEM_BYTES);
    cudaFuncSetAttribute(k_gemmB, cudaFuncAttributeMaxDynamicSharedMemorySize, SMEM_BYTES);

    int nsub = BB * LC + BB * LQ;
    k_sub<<<(nsub + 255) / 256, 256>>>(C, Q, w4C, w4Q, bias);
    k_scores<<<dim3(4, 16, 16), 256, SMEM_BYTES>>>(C, Q, w4mlu);
    k_rowstats<<<(BB * LC) / 8, 256>>>(Qmask);
    k_colstats_part<<<dim3(16, 4, 16), 256>>>(Cmask);
    k_colstats_merge<<<32, 256>>>();
    k_gemmA<<<dim3(16, 16), 256, SMEM_BYTES>>>(Q, Qmask);
    k_gemmV2<<<dim3(4, 4, 16), 256, SMEM_BYTES>>>(C, Cmask);
    k_reduceV2<<<(BB * LQ * DD / 4 + 255) / 256, 256>>>();
    k_gemmB<<<dim3(16, 16), 256, SMEM_BYTES>>>(Qmask);
    k_assemble<<<dim3(64, 4, 16), dim3(32, 8)>>>(C, out);
}